// round 16
// baseline (speedup 1.0000x reference)
#include <cuda_runtime.h>
#include <math.h>

// ---------------- problem constants ----------------
#define BATCH 256
#define C1_IC 3
#define C1_OC 6
#define C1_IH 250
#define C1_OH 124
#define P1_OH 123
#define C2_IC 6
#define C2_OC 15
#define C2_OH 62
#define P2_OH 61
#define FC1_IN 55815   // 15*61*61
#define FC1_OUT 120
#define FC2_OUT 84

typedef unsigned long long ull;

// ---------------- f32x2 packed helpers ----------------
__device__ __forceinline__ ull pk2(float lo, float hi) {
    ull r; asm("mov.b64 %0, {%1,%2};" : "=l"(r) : "f"(lo), "f"(hi)); return r;
}
__device__ __forceinline__ void upk2(float& lo, float& hi, ull v) {
    asm("mov.b64 {%0,%1}, %2;" : "=f"(lo), "=f"(hi) : "l"(v));
}
__device__ __forceinline__ void fma2(ull& d, ull a, ull b) {
    asm("fma.rn.f32x2 %0, %1, %2, %3;" : "=l"(d) : "l"(a), "l"(b), "l"(d));
}

// ---------------- device scratch ----------------
__device__ float g_p1[BATCH * C1_OC * P1_OH * P1_OH];     // 93 MB
__device__ float g_p2[BATCH * C2_OC * P2_OH * P2_OH];     // 57 MB (fc1 input)
__device__ float g_fc1p[74 * BATCH * FC1_OUT];            // K-split partials (9.1 MB)
__device__ float g_h1[BATCH * FC1_OUT];
__device__ float g_feat[BATCH * FC2_OUT];
__device__ float g_probs[BATCH];

#define C1_NP 3                         // conv1 oc pairs (6 oc)
#define C2_NP 8                         // conv2 oc pairs (15 oc padded to 16)
__device__ float2 g_w1p[C1_IC * 25 * C1_NP];
__device__ float2 g_w2p[C2_IC * 9 * C2_NP];
__device__ float  g_b1[8];
__device__ float  g_b2[16];

// ====== prep kernels (2 launches; conv2 stays at profiled idx 3) =====
__global__ void pack_w1_kernel(const float* __restrict__ w, const float* __restrict__ b1) {
    int i = threadIdx.x;
    if (i < C1_IC * 25 * C1_NP) {
        int q = i % C1_NP, rest = i / C1_NP;
        int ic = rest / 25, t = rest % 25;
        g_w1p[i] = make_float2(w[((2 * q) * C1_IC + ic) * 25 + t],
                               w[((2 * q + 1) * C1_IC + ic) * 25 + t]);
    }
    if (i >= 232 && i < 240) {
        int k = i - 232;
        g_b1[k] = (k < C1_OC) ? b1[k] : 0.f;
    }
}
__global__ void pack_w2_kernel(const float* __restrict__ w, const float* __restrict__ b2) {
    int i = threadIdx.x;
    if (i < C2_IC * 9 * C2_NP) {
        int q = i % C2_NP, rest = i / C2_NP;
        int ic = rest / 9, t = rest % 9;
        int oc0 = 2 * q, oc1 = 2 * q + 1;
        float w0 = (oc0 < C2_OC) ? w[(oc0 * C2_IC + ic) * 9 + t] : 0.f;
        float w1 = (oc1 < C2_OC) ? w[(oc1 * C2_IC + ic) * 9 + t] : 0.f;
        g_w2p[i] = make_float2(w0, w1);
    }
    if (i >= 432 && i < 448) {
        int k = i - 432;
        g_b2[k] = (k < C2_OC) ? b2[k] : 0.f;
    }
}

// ====== conv1: dup-x smem + SMEM weights (LDS broadcast, avoids LDC floor-8 port) ======
#define C1_TPX 32
#define C1_TPY 16
#define C1_CW 33
#define C1_CH 17
#define C1_XW 69                        // (33-1)*2+5
#define C1_DUP_W 70                     // ull (x,x) pairs per row, padded
#define C1_XH 37                        // (17-1)*2+5
#define C1_T 128
#define C1_DUP_SZ (C1_XH * C1_DUP_W)        // 2590 ull = 20720 B (16B-divisible)
#define C1_CB_SZ (C1_OC * C1_CH * C1_CW)    // 3366 floats = 13464 B (< dup)
#define C1_SW_SZ (C1_IC * 25 * C1_NP)       // 225 float2
#define C1_SMEM_BYTES (C1_DUP_SZ * 8 + C1_SW_SZ * 8 + 64)   // ~22.6 KB

__global__ __launch_bounds__(C1_T)
void conv1_pool_kernel(const float* __restrict__ x) {
    extern __shared__ __align__(16) float smem1[];
    ull*    dup  = (ull*)smem1;                  // (v,v) pairs during conv
    float*  cbuf = smem1;                        // conv output after (union w/ dup)
    float2* sw2  = (float2*)(smem1 + 2 * C1_DUP_SZ);  // byte off 20720 ≡ 0 mod 16
    float*  sb   = (float*)(sw2 + C1_SW_SZ);

    const int tid = threadIdx.x;
    const int b   = blockIdx.z;
    const int px0 = blockIdx.x * C1_TPX;
    const int py0 = blockIdx.y * C1_TPY;
    const int ix0 = px0 * 2 - 1;
    const int iy0 = py0 * 2 - 1;

    for (int i = tid; i < C1_SW_SZ; i += C1_T) sw2[i] = g_w1p[i];
    if (tid < C1_OC) sb[tid] = g_b1[tid];

    const int row = tid / 7;              // conv row 0..18 (17 valid)
    const int cx0 = (tid % 7) * 5;        // strip start col

    ull acc[5][C1_NP];
#pragma unroll
    for (int u = 0; u < 5; u++)
#pragma unroll
        for (int q = 0; q < C1_NP; q++) acc[u][q] = 0ull;

    const float* xb = x + (long)b * C1_IC * C1_IH * C1_IH;
#pragma unroll 1
    for (int ic = 0; ic < C1_IC; ic++) {
        __syncthreads();
        const float* xc = xb + ic * C1_IH * C1_IH;
        for (int i = tid; i < C1_XH * C1_XW; i += C1_T) {
            int r = i / C1_XW, c = i % C1_XW;
            int iy = iy0 + r, ix = ix0 + c;
            float v = 0.f;
            if (iy >= 0 && iy < C1_IH && ix >= 0 && ix < C1_IH)
                v = xc[iy * C1_IH + ix];
            dup[r * C1_DUP_W + c] = pk2(v, v);
        }
        __syncthreads();

        if (row < C1_CH) {
#pragma unroll
            for (int ky = 0; ky < 5; ky++) {
                const ull* xr = &dup[(row * 2 + ky) * C1_DUP_W + cx0 * 2];
                ull xx[13];
#pragma unroll
                for (int o = 0; o < 13; o++) xx[o] = xr[o];   // LDS.64 (v,v) direct
                const float2* wp = &sw2[(ic * 25 + ky * 5) * C1_NP];
#pragma unroll
                for (int kx = 0; kx < 5; kx++) {
                    ull w2[C1_NP];
#pragma unroll
                    for (int q = 0; q < C1_NP; q++)
                        w2[q] = *(const ull*)&wp[kx * C1_NP + q];  // broadcast LDS.64
#pragma unroll
                    for (int u = 0; u < 5; u++)
#pragma unroll
                        for (int q = 0; q < C1_NP; q++)
                            fma2(acc[u][q], xx[2 * u + kx], w2[q]);
                }
            }
        }
    }
    __syncthreads();   // all dup reads done; smem becomes cbuf

    if (row < C1_CH) {
#pragma unroll
        for (int u = 0; u < 5; u++) {
            int cx = cx0 + u;
            if (cx < C1_CW) {
#pragma unroll
                for (int q = 0; q < C1_NP; q++) {
                    float lo, hi; upk2(lo, hi, acc[u][q]);
                    cbuf[(2 * q) * (C1_CH * C1_CW) + row * C1_CW + cx]     = fmaxf(lo + sb[2 * q], 0.f);
                    cbuf[(2 * q + 1) * (C1_CH * C1_CW) + row * C1_CW + cx] = fmaxf(hi + sb[2 * q + 1], 0.f);
                }
            }
        }
    }
    __syncthreads();

    for (int m = tid; m < C1_OC * C1_TPY * C1_TPX; m += C1_T) {
        int oc  = m >> 9;
        int rem = m & 511;
        int pyl = rem >> 5, pxl = rem & 31;
        int px = px0 + pxl, py = py0 + pyl;
        if (px < P1_OH && py < P1_OH) {
            const float* cb = &cbuf[oc * (C1_CH * C1_CW) + pyl * C1_CW + pxl];
            float v = fmaxf(fmaxf(cb[0], cb[1]), fmaxf(cb[C1_CW], cb[C1_CW + 1]));
            g_p1[((long)(b * C1_OC + oc) * P1_OH + py) * P1_OH + px] = v;
        }
    }
}

// ====== conv2: oc split, R12 x-path, SMEM weights ======
#define C2_TPX 32
#define C2_TPY 16
#define C2_CW 33
#define C2_CH 17
#define C2_XW 67                       // (33-1)*2+3
#define C2_XWP 72                      // even pad
#define C2_XH 35                       // (17-1)*2+3
#define C2_T 256
#define C2_NQ 4                        // oc pairs per thread (2 groups x 4 = 8)
#define C2_CB_SZ 8416                                  // union buffer (8415 padded even)
#define C2_SW_SZ (C2_IC * 9 * C2_NP)                   // 432 float2
#define C2_SMEM_BYTES (C2_CB_SZ * 4 + C2_SW_SZ * 8 + 64)   // ~37.2 KB

__global__ __launch_bounds__(C2_T, 3)
void conv2_pool_kernel() {
    extern __shared__ __align__(16) float smem[];
    float*  buf = smem;                           // xs during conv; cbuf after
    float2* sw2 = (float2*)(buf + C2_CB_SZ);      // 8416*4=33664 ≡ 0 mod 16
    float*  sb  = (float*)(sw2 + C2_SW_SZ);

    const int tid = threadIdx.x;
    const int b   = blockIdx.z;
    const int px0 = blockIdx.x * C2_TPX;
    const int py0 = blockIdx.y * C2_TPY;
    const int ix0 = px0 * 2 - 1;
    const int iy0 = py0 * 2 - 1;

    for (int i = tid; i < C2_SW_SZ; i += C2_T) sw2[i] = g_w2p[i];
    if (tid < C2_OC) sb[tid] = g_b2[tid];

    const int ocg = tid & 1;              // oc group: pairs ocg*4 .. ocg*4+3
    const int pos = tid >> 1;             // 0..127 (119 valid)
    const int row = pos / 7;
    const int cx0 = (pos % 7) * 5;
    const bool act = (row < C2_CH);

    ull acc[5][C2_NQ];
#pragma unroll
    for (int u = 0; u < 5; u++)
#pragma unroll
        for (int q = 0; q < C2_NQ; q++) acc[u][q] = 0ull;

    const float* xb = g_p1 + (long)b * C2_IC * P1_OH * P1_OH;
#pragma unroll 1
    for (int ic = 0; ic < C2_IC; ic++) {
        __syncthreads();
        const float* xc = xb + ic * P1_OH * P1_OH;
        for (int i = tid; i < C2_XH * C2_XW; i += C2_T) {
            int r = i / C2_XW, c = i % C2_XW;
            int iy = iy0 + r, ix = ix0 + c;
            float v = 0.f;
            if (iy >= 0 && iy < P1_OH && ix >= 0 && ix < P1_OH)
                v = xc[iy * P1_OH + ix];
            buf[r * C2_XWP + c] = v;
        }
        __syncthreads();

        if (act) {
#pragma unroll
            for (int ky = 0; ky < 3; ky++) {
                const float2* xr2 = (const float2*)&buf[(row * 2 + ky) * C2_XWP + cx0 * 2];
                float2 f[6];
#pragma unroll
                for (int o = 0; o < 6; o++) f[o] = xr2[o];
                const float2* wp = &sw2[(ic * 9 + ky * 3) * C2_NP + ocg * C2_NQ];
#pragma unroll
                for (int kx = 0; kx < 3; kx++) {
                    ull w2[C2_NQ];
#pragma unroll
                    for (int q = 0; q < C2_NQ; q++)
                        w2[q] = *(const ull*)&wp[kx * C2_NP + q];
#pragma unroll
                    for (int u = 0; u < 5; u++) {
                        int o = 2 * u + kx;
                        float v = (o & 1) ? f[o >> 1].y : f[o >> 1].x;
                        ull xv = pk2(v, v);
#pragma unroll
                        for (int q = 0; q < C2_NQ; q++)
                            fma2(acc[u][q], xv, w2[q]);
                    }
                }
            }
        }
    }
    __syncthreads();   // all xs reads done; buf becomes cbuf

    if (act) {
#pragma unroll
        for (int u = 0; u < 5; u++) {
            int cx = cx0 + u;
            if (cx < C2_CW) {
#pragma unroll
                for (int q = 0; q < C2_NQ; q++) {
                    int qg  = ocg * C2_NQ + q;
                    int oc0 = 2 * qg, oc1 = 2 * qg + 1;
                    float lo, hi; upk2(lo, hi, acc[u][q]);
                    buf[oc0 * (C2_CH * C2_CW) + row * C2_CW + cx] = fmaxf(lo + sb[oc0], 0.f);
                    if (oc1 < C2_OC)
                        buf[oc1 * (C2_CH * C2_CW) + row * C2_CW + cx] = fmaxf(hi + sb[oc1], 0.f);
                }
            }
        }
    }
    __syncthreads();

    for (int m = tid; m < C2_OC * C2_TPY * C2_TPX; m += C2_T) {
        int oc  = m >> 9;
        int rem = m & 511;
        int pyl = rem >> 5, pxl = rem & 31;
        int px = px0 + pxl, py = py0 + pyl;
        if (px < P2_OH && py < P2_OH) {
            const float* cb = &buf[oc * (C2_CH * C2_CW) + pyl * C2_CW + pxl];
            float v = fmaxf(fmaxf(cb[0], cb[1]), fmaxf(cb[C2_CW], cb[C2_CW + 1]));
            g_p2[((long)(b * C2_OC + oc) * P2_OH + py) * P2_OH + px] = v;
        }
    }
}

// ===== fc1: exact R12 form — grid(2,74)=148 blocks (one wave), FFMA2, reg-prefetch =====
#define KSPLIT 74
#define KCHUNK 768     // 74*768 = 56832 >= 55815
#define KT 32
#define BSROW 130

__global__ __launch_bounds__(256)
void fc1_kernel(const float* __restrict__ wfc) {
    __shared__ float As[128][KT + 1];
    __shared__ __align__(16) float Bs[KT][BSROW];

    const int m0   = blockIdx.x * 128;
    const int kb   = blockIdx.y;
    const int tid  = threadIdx.x;
    const int tx   = tid & 15;
    const int ty   = tid >> 4;

    ull acc[8][4];
#pragma unroll
    for (int i = 0; i < 8; i++)
#pragma unroll
        for (int q = 0; q < 4; q++) acc[i][q] = 0ull;

    float rA[16], rB[16];
    int k0 = kb * KCHUNK;
#pragma unroll
    for (int t = 0; t < 16; t++) {
        int i = t * 256 + tid;
        int r = i >> 5, c = i & 31;
        int k = k0 + c;
        rA[t] = (k < FC1_IN) ? g_p2[(long)(m0 + r) * FC1_IN + k] : 0.f;
        rB[t] = (r < FC1_OUT && k < FC1_IN) ? wfc[(long)r * FC1_IN + k] : 0.f;
    }

#pragma unroll 1
    for (int step = 0; step < KCHUNK / KT; step++) {
#pragma unroll
        for (int t = 0; t < 16; t++) {
            int i = t * 256 + tid;
            int r = i >> 5, c = i & 31;
            As[r][c] = rA[t];
            Bs[c][r] = rB[t];
        }
        __syncthreads();

        int k1 = k0 + KT;
        if (step + 1 < KCHUNK / KT) {
#pragma unroll
            for (int t = 0; t < 16; t++) {
                int i = t * 256 + tid;
                int r = i >> 5, c = i & 31;
                int k = k1 + c;
                rA[t] = (k < FC1_IN) ? g_p2[(long)(m0 + r) * FC1_IN + k] : 0.f;
                rB[t] = (r < FC1_OUT && k < FC1_IN) ? wfc[(long)r * FC1_IN + k] : 0.f;
            }
        }

#pragma unroll 4
        for (int kk = 0; kk < KT; kk++) {
            ull b2[4], a2[8];
            const ull* bp = (const ull*)&Bs[kk][0];
#pragma unroll
            for (int q = 0; q < 4; q++) b2[q] = bp[tx + 16 * q];
#pragma unroll
            for (int i = 0; i < 8; i++) { float av = As[ty + 16 * i][kk]; a2[i] = pk2(av, av); }
#pragma unroll
            for (int i = 0; i < 8; i++)
#pragma unroll
                for (int q = 0; q < 4; q++) fma2(acc[i][q], a2[i], b2[q]);
        }
        k0 = k1;
        __syncthreads();
    }

#pragma unroll
    for (int i = 0; i < 8; i++) {
        int m = m0 + ty + 16 * i;
#pragma unroll
        for (int q = 0; q < 4; q++) {
            float lo, hi; upk2(lo, hi, acc[i][q]);
            int n = 2 * (tx + 16 * q);
            if (n < FC1_OUT)     g_fc1p[((long)kb * BATCH + m) * FC1_OUT + n]     = lo;
            if (n + 1 < FC1_OUT) g_fc1p[((long)kb * BATCH + m) * FC1_OUT + n + 1] = hi;
        }
    }
}

__global__ void fc1_reduce_kernel(const float* __restrict__ bias) {
    int idx = blockIdx.x * blockDim.x + threadIdx.x;
    if (idx >= BATCH * FC1_OUT) return;
    int n = idx % FC1_OUT;
    float s = bias[n];
#pragma unroll 2
    for (int kb = 0; kb < KSPLIT; kb++)
        s += g_fc1p[(long)kb * BATCH * FC1_OUT + idx];
    g_h1[idx] = fmaxf(s, 0.f);
}

// ================= fc2 + head fused =================
__global__ __launch_bounds__(128)
void fc2_head_kernel(const float* __restrict__ w, const float* __restrict__ bias,
                     const float* __restrict__ fc3w, const float* __restrict__ fc3b,
                     const float* __restrict__ plw, const float* __restrict__ plb,
                     const float* __restrict__ pls, const float* __restrict__ plbias) {
    int b = blockIdx.x;
    int tid = threadIdx.x;
    __shared__ float h[FC1_OUT];
    __shared__ float fs[FC2_OUT];
    __shared__ float wsum[4];

    if (tid < FC1_OUT) h[tid] = g_h1[b * FC1_OUT + tid];
    __syncthreads();
    if (tid < FC2_OUT) {
        float s = bias[tid];
        const float* wr = w + tid * FC1_OUT;
#pragma unroll 8
        for (int k = 0; k < FC1_OUT; k++) s = fmaf(h[k], wr[k], s);
        fs[tid] = s;
        g_feat[b * FC2_OUT + tid] = s;
    }
    __syncthreads();

    float p = (tid < FC2_OUT) ? fs[tid] * fc3w[tid] : 0.f;
#pragma unroll
    for (int o = 16; o > 0; o >>= 1) p += __shfl_xor_sync(0xffffffff, p, o);
    if ((tid & 31) == 0) wsum[tid >> 5] = p;
    __syncthreads();
    if (tid == 0) {
        float s = wsum[0] + wsum[1] + wsum[2] + wsum[3] + fc3b[0];
        float z = tanhf(s * plw[0] + plb[0]) * pls[0] + plbias[0];
        g_probs[b] = 1.f / (1.f + expf(-z));
    }
}

// ====== graph aggregation (sign(dot) == sign(sim), THRESH=0), shuffle reduction ========
__global__ void graph_kernel(float* __restrict__ out) {
    int i = blockIdx.x;
    int j = threadIdx.x;
    __shared__ float fi[FC2_OUT];
    __shared__ float wdeg[8];
    __shared__ float wsm[8];
    if (j < FC2_OUT) fi[j] = g_feat[i * FC2_OUT + j];
    __syncthreads();

    float dot = 0.f;
#pragma unroll 4
    for (int k = 0; k < FC2_OUT; k++) dot = fmaf(fi[k], g_feat[j * FC2_OUT + k], dot);
    float a = (dot >= 0.f && i != j) ? 1.f : 0.f;
    float s = a * g_probs[j];

#pragma unroll
    for (int o = 16; o > 0; o >>= 1) {
        a += __shfl_xor_sync(0xffffffff, a, o);
        s += __shfl_xor_sync(0xffffffff, s, o);
    }
    if ((j & 31) == 0) { wdeg[j >> 5] = a; wsm[j >> 5] = s; }
    __syncthreads();
    if (j == 0) {
        float deg = 0.f, sm = 0.f;
#pragma unroll
        for (int w = 0; w < 8; w++) { deg += wdeg[w]; sm += wsm[w]; }
        float nm  = (deg > 0.f) ? (sm / fmaxf(deg, 1.f)) : 0.f;
        float agg = (g_probs[i] + nm) / (1.f + deg);
        out[i * 2 + 0] = agg;
        out[i * 2 + 1] = 1.f - agg;
    }
}

// ================= launch =================
extern "C" void kernel_launch(void* const* d_in, const int* in_sizes, int n_in,
                              void* d_out, int out_size) {
    const float* x       = (const float*)d_in[0];
    const float* conv1_w = (const float*)d_in[1];
    const float* conv1_b = (const float*)d_in[2];
    const float* conv2_w = (const float*)d_in[3];
    const float* conv2_b = (const float*)d_in[4];
    const float* fc1_w   = (const float*)d_in[5];
    const float* fc1_b   = (const float*)d_in[6];
    const float* fc2_w   = (const float*)d_in[7];
    const float* fc2_b   = (const float*)d_in[8];
    const float* fc3_w   = (const float*)d_in[9];
    const float* fc3_b   = (const float*)d_in[10];
    const float* pl_w    = (const float*)d_in[11];
    const float* pl_b    = (const float*)d_in[12];
    const float* pl_s    = (const float*)d_in[13];
    const float* pl_bias = (const float*)d_in[14];
    float* out = (float*)d_out;

    cudaFuncSetAttribute(conv1_pool_kernel,
                         cudaFuncAttributeMaxDynamicSharedMemorySize, C1_SMEM_BYTES);
    cudaFuncSetAttribute(conv2_pool_kernel,
                         cudaFuncAttributeMaxDynamicSharedMemorySize, C2_SMEM_BYTES);

    // prep: pack into device globals (2 kernel launches)
    pack_w1_kernel<<<1, 256>>>(conv1_w, conv1_b);     // launch 0
    pack_w2_kernel<<<1, 448>>>(conv2_w, conv2_b);     // launch 1

    {   // conv1 + relu + pool1 (fused) — launch 2
        dim3 grd((P1_OH + C1_TPX - 1) / C1_TPX, (P1_OH + C1_TPY - 1) / C1_TPY, BATCH);
        conv1_pool_kernel<<<grd, C1_T, C1_SMEM_BYTES>>>(x);
    }
    {   // conv2 + relu + pool2 (fused) — launch 3 (profiled)
        dim3 grd((P2_OH + C2_TPX - 1) / C2_TPX, (P2_OH + C2_TPY - 1) / C2_TPY, BATCH);
        conv2_pool_kernel<<<grd, C2_T, C2_SMEM_BYTES>>>();
    }
    // fc1 (one wave: 148 blocks) + reduce
    {
        dim3 grd(2, KSPLIT);
        fc1_kernel<<<grd, 256>>>(fc1_w);
        fc1_reduce_kernel<<<(BATCH * FC1_OUT + 127) / 128, 128>>>(fc1_b);
    }
    fc2_head_kernel<<<BATCH, 128>>>(fc2_w, fc2_b, fc3_w, fc3_b, pl_w, pl_b, pl_s, pl_bias);
    graph_kernel<<<BATCH, BATCH>>>(out);
}

// round 17
// speedup vs baseline: 1.0648x; 1.0648x over previous
#include <cuda_runtime.h>
#include <math.h>

// ---------------- problem constants ----------------
#define BATCH 256
#define C1_IC 3
#define C1_OC 6
#define C1_IH 250
#define C1_OH 124
#define P1_OH 123
#define C2_IC 6
#define C2_OC 15
#define C2_OH 62
#define P2_OH 61
#define FC1_IN 55815   // 15*61*61
#define FC1_OUT 120
#define FC2_OUT 84

typedef unsigned long long ull;

// ---------------- f32x2 packed helpers ----------------
__device__ __forceinline__ ull pk2(float lo, float hi) {
    ull r; asm("mov.b64 %0, {%1,%2};" : "=l"(r) : "f"(lo), "f"(hi)); return r;
}
__device__ __forceinline__ void upk2(float& lo, float& hi, ull v) {
    asm("mov.b64 {%0,%1}, %2;" : "=f"(lo), "=f"(hi) : "l"(v));
}
__device__ __forceinline__ void fma2(ull& d, ull a, ull b) {
    asm("fma.rn.f32x2 %0, %1, %2, %3;" : "=l"(d) : "l"(a), "l"(b), "l"(d));
}

// ---------------- device scratch ----------------
__device__ float g_p1[BATCH * C1_OC * P1_OH * P1_OH];     // 93 MB
__device__ float g_p2[BATCH * C2_OC * P2_OH * P2_OH];     // 57 MB (fc1 input)
__device__ float g_fc1p[74 * BATCH * FC1_OUT];            // K-split partials (9.1 MB)
__device__ float g_h1[BATCH * FC1_OUT];
__device__ float g_feat[BATCH * FC2_OUT];
__device__ float g_probs[BATCH];

#define C1_NP 3                         // conv1 oc pairs (6 oc)
#define C2_NP 8                         // conv2 oc pairs (15 oc padded to 16)
__device__ float2 g_w1p[C1_IC * 25 * C1_NP];
__device__ float2 g_w2p[C2_IC * 9 * C2_NP];
__device__ float  g_b1[8];
__device__ float  g_b2[16];

// ---------------- constant-memory weights (measured better than smem) ----------------
__constant__ float2 c_w1[C1_IC * 25 * C1_NP];   // 1.8 KB
__constant__ float2 c_w2[C2_IC * 9 * C2_NP];    // 3.5 KB
__constant__ float  c_b1[8];
__constant__ float  c_b2[16];

// ====== prep kernels (2 launches; conv2 stays at profiled idx 3) =====
__global__ void pack_w1_kernel(const float* __restrict__ w, const float* __restrict__ b1) {
    int i = threadIdx.x;
    if (i < C1_IC * 25 * C1_NP) {
        int q = i % C1_NP, rest = i / C1_NP;
        int ic = rest / 25, t = rest % 25;
        g_w1p[i] = make_float2(w[((2 * q) * C1_IC + ic) * 25 + t],
                               w[((2 * q + 1) * C1_IC + ic) * 25 + t]);
    }
    if (i >= 232 && i < 240) {
        int k = i - 232;
        g_b1[k] = (k < C1_OC) ? b1[k] : 0.f;
    }
}
__global__ void pack_w2_kernel(const float* __restrict__ w, const float* __restrict__ b2) {
    int i = threadIdx.x;
    if (i < C2_IC * 9 * C2_NP) {
        int q = i % C2_NP, rest = i / C2_NP;
        int ic = rest / 9, t = rest % 9;
        int oc0 = 2 * q, oc1 = 2 * q + 1;
        float w0 = (oc0 < C2_OC) ? w[(oc0 * C2_IC + ic) * 9 + t] : 0.f;
        float w1 = (oc1 < C2_OC) ? w[(oc1 * C2_IC + ic) * 9 + t] : 0.f;
        g_w2p[i] = make_float2(w0, w1);
    }
    if (i >= 432 && i < 448) {
        int k = i - 432;
        g_b2[k] = (k < C2_OC) ? b2[k] : 0.f;
    }
}

// ====== conv1: dup-x smem + __constant__ weights (measured best conv1) ======
#define C1_TPX 32
#define C1_TPY 16
#define C1_CW 33
#define C1_CH 17
#define C1_XW 69                        // (33-1)*2+5
#define C1_DUP_W 70                     // ull (x,x) pairs per row, padded
#define C1_XH 37                        // (17-1)*2+5
#define C1_T 128
#define C1_DUP_SZ (C1_XH * C1_DUP_W)        // 2590 ull = 20720 B
#define C1_CB_SZ (C1_OC * C1_CH * C1_CW)    // 3366 floats = 13464 B (< dup)
#define C1_SMEM_BYTES (C1_DUP_SZ * 8 + 64)  // ~20.8 KB

__global__ __launch_bounds__(C1_T)
void conv1_pool_kernel(const float* __restrict__ x) {
    extern __shared__ __align__(16) float smem1[];
    ull*   dup  = (ull*)smem1;                  // (v,v) pairs during conv
    float* cbuf = smem1;                        // conv output after (union)

    const int tid = threadIdx.x;
    const int b   = blockIdx.z;
    const int px0 = blockIdx.x * C1_TPX;
    const int py0 = blockIdx.y * C1_TPY;
    const int ix0 = px0 * 2 - 1;
    const int iy0 = py0 * 2 - 1;

    const int row = tid / 7;              // conv row 0..18 (17 valid)
    const int cx0 = (tid % 7) * 5;        // strip start col

    ull acc[5][C1_NP];
#pragma unroll
    for (int u = 0; u < 5; u++)
#pragma unroll
        for (int q = 0; q < C1_NP; q++) acc[u][q] = 0ull;

    const float* xb = x + (long)b * C1_IC * C1_IH * C1_IH;
#pragma unroll 1
    for (int ic = 0; ic < C1_IC; ic++) {
        __syncthreads();
        const float* xc = xb + ic * C1_IH * C1_IH;
        for (int i = tid; i < C1_XH * C1_XW; i += C1_T) {
            int r = i / C1_XW, c = i % C1_XW;
            int iy = iy0 + r, ix = ix0 + c;
            float v = 0.f;
            if (iy >= 0 && iy < C1_IH && ix >= 0 && ix < C1_IH)
                v = xc[iy * C1_IH + ix];
            dup[r * C1_DUP_W + c] = pk2(v, v);
        }
        __syncthreads();

        if (row < C1_CH) {
#pragma unroll
            for (int ky = 0; ky < 5; ky++) {
                const ull* xr = &dup[(row * 2 + ky) * C1_DUP_W + cx0 * 2];
                ull xx[13];
#pragma unroll
                for (int o = 0; o < 13; o++) xx[o] = xr[o];   // LDS.64 (v,v) direct
                const float2* wp = &c_w1[(ic * 25 + ky * 5) * C1_NP];
#pragma unroll
                for (int kx = 0; kx < 5; kx++) {
                    ull w2[C1_NP];
#pragma unroll
                    for (int q = 0; q < C1_NP; q++)
                        w2[q] = *(const ull*)&wp[kx * C1_NP + q];
#pragma unroll
                    for (int u = 0; u < 5; u++)
#pragma unroll
                        for (int q = 0; q < C1_NP; q++)
                            fma2(acc[u][q], xx[2 * u + kx], w2[q]);
                }
            }
        }
    }
    __syncthreads();   // all dup reads done; smem becomes cbuf

    if (row < C1_CH) {
#pragma unroll
        for (int u = 0; u < 5; u++) {
            int cx = cx0 + u;
            if (cx < C1_CW) {
#pragma unroll
                for (int q = 0; q < C1_NP; q++) {
                    float lo, hi; upk2(lo, hi, acc[u][q]);
                    cbuf[(2 * q) * (C1_CH * C1_CW) + row * C1_CW + cx]     = fmaxf(lo + c_b1[2 * q], 0.f);
                    cbuf[(2 * q + 1) * (C1_CH * C1_CW) + row * C1_CW + cx] = fmaxf(hi + c_b1[2 * q + 1], 0.f);
                }
            }
        }
    }
    __syncthreads();

    for (int m = tid; m < C1_OC * C1_TPY * C1_TPX; m += C1_T) {
        int oc  = m >> 9;
        int rem = m & 511;
        int pyl = rem >> 5, pxl = rem & 31;
        int px = px0 + pxl, py = py0 + pyl;
        if (px < P1_OH && py < P1_OH) {
            const float* cb = &cbuf[oc * (C1_CH * C1_CW) + pyl * C1_CW + pxl];
            float v = fmaxf(fmaxf(cb[0], cb[1]), fmaxf(cb[C1_CW], cb[C1_CW + 1]));
            g_p1[((long)(b * C1_OC + oc) * P1_OH + py) * P1_OH + px] = v;
        }
    }
}

// ====== conv2: exact R12 form — oc split, float2 x-path, __constant__ weights ======
#define C2_TPX 32
#define C2_TPY 16
#define C2_CW 33
#define C2_CH 17
#define C2_XW 67                       // (33-1)*2+3
#define C2_XWP 72                      // even pad
#define C2_XH 35                       // (17-1)*2+3
#define C2_T 256
#define C2_NQ 4                        // oc pairs per thread (2 groups x 4 = 8)
#define C2_CB_SZ 8416                                  // union buffer (8415 padded even)
#define C2_SMEM_BYTES (C2_CB_SZ * 4 + 64)              // ~33.7 KB

__global__ __launch_bounds__(C2_T, 3)
void conv2_pool_kernel() {
    extern __shared__ __align__(16) float smem[];
    float* buf = smem;                           // xs during conv; cbuf after

    const int tid = threadIdx.x;
    const int b   = blockIdx.z;
    const int px0 = blockIdx.x * C2_TPX;
    const int py0 = blockIdx.y * C2_TPY;
    const int ix0 = px0 * 2 - 1;
    const int iy0 = py0 * 2 - 1;

    const int ocg = tid & 1;              // oc group: pairs ocg*4 .. ocg*4+3
    const int pos = tid >> 1;             // 0..127 (119 valid)
    const int row = pos / 7;
    const int cx0 = (pos % 7) * 5;
    const bool act = (row < C2_CH);

    ull acc[5][C2_NQ];
#pragma unroll
    for (int u = 0; u < 5; u++)
#pragma unroll
        for (int q = 0; q < C2_NQ; q++) acc[u][q] = 0ull;

    const float* xb = g_p1 + (long)b * C2_IC * P1_OH * P1_OH;
#pragma unroll 1
    for (int ic = 0; ic < C2_IC; ic++) {
        __syncthreads();
        const float* xc = xb + ic * P1_OH * P1_OH;
        for (int i = tid; i < C2_XH * C2_XW; i += C2_T) {
            int r = i / C2_XW, c = i % C2_XW;
            int iy = iy0 + r, ix = ix0 + c;
            float v = 0.f;
            if (iy >= 0 && iy < P1_OH && ix >= 0 && ix < P1_OH)
                v = xc[iy * P1_OH + ix];
            buf[r * C2_XWP + c] = v;
        }
        __syncthreads();

        if (act) {
#pragma unroll
            for (int ky = 0; ky < 3; ky++) {
                const float2* xr2 = (const float2*)&buf[(row * 2 + ky) * C2_XWP + cx0 * 2];
                float2 f[6];
#pragma unroll
                for (int o = 0; o < 6; o++) f[o] = xr2[o];
                const float2* wp = &c_w2[(ic * 9 + ky * 3) * C2_NP + ocg * C2_NQ];
#pragma unroll
                for (int kx = 0; kx < 3; kx++) {
                    ull w2[C2_NQ];
#pragma unroll
                    for (int q = 0; q < C2_NQ; q++)
                        w2[q] = *(const ull*)&wp[kx * C2_NP + q];
#pragma unroll
                    for (int u = 0; u < 5; u++) {
                        int o = 2 * u + kx;
                        float v = (o & 1) ? f[o >> 1].y : f[o >> 1].x;
                        ull xv = pk2(v, v);
#pragma unroll
                        for (int q = 0; q < C2_NQ; q++)
                            fma2(acc[u][q], xv, w2[q]);
                    }
                }
            }
        }
    }
    __syncthreads();   // all xs reads done; buf becomes cbuf

    if (act) {
#pragma unroll
        for (int u = 0; u < 5; u++) {
            int cx = cx0 + u;
            if (cx < C2_CW) {
#pragma unroll
                for (int q = 0; q < C2_NQ; q++) {
                    int qg  = ocg * C2_NQ + q;
                    int oc0 = 2 * qg, oc1 = 2 * qg + 1;
                    float lo, hi; upk2(lo, hi, acc[u][q]);
                    buf[oc0 * (C2_CH * C2_CW) + row * C2_CW + cx] = fmaxf(lo + c_b2[oc0], 0.f);
                    if (oc1 < C2_OC)
                        buf[oc1 * (C2_CH * C2_CW) + row * C2_CW + cx] = fmaxf(hi + c_b2[oc1], 0.f);
                }
            }
        }
    }
    __syncthreads();

    for (int m = tid; m < C2_OC * C2_TPY * C2_TPX; m += C2_T) {
        int oc  = m >> 9;
        int rem = m & 511;
        int pyl = rem >> 5, pxl = rem & 31;
        int px = px0 + pxl, py = py0 + pyl;
        if (px < P2_OH && py < P2_OH) {
            const float* cb = &buf[oc * (C2_CH * C2_CW) + pyl * C2_CW + pxl];
            float v = fmaxf(fmaxf(cb[0], cb[1]), fmaxf(cb[C2_CW], cb[C2_CW + 1]));
            g_p2[((long)(b * C2_OC + oc) * P2_OH + py) * P2_OH + px] = v;
        }
    }
}

// ===== fc1: exact R12 form — grid(2,74)=148 blocks (one wave), FFMA2, reg-prefetch =====
#define KSPLIT 74
#define KCHUNK 768     // 74*768 = 56832 >= 55815
#define KT 32
#define BSROW 130

__global__ __launch_bounds__(256)
void fc1_kernel(const float* __restrict__ wfc) {
    __shared__ float As[128][KT + 1];
    __shared__ __align__(16) float Bs[KT][BSROW];

    const int m0   = blockIdx.x * 128;
    const int kb   = blockIdx.y;
    const int tid  = threadIdx.x;
    const int tx   = tid & 15;
    const int ty   = tid >> 4;

    ull acc[8][4];
#pragma unroll
    for (int i = 0; i < 8; i++)
#pragma unroll
        for (int q = 0; q < 4; q++) acc[i][q] = 0ull;

    float rA[16], rB[16];
    int k0 = kb * KCHUNK;
#pragma unroll
    for (int t = 0; t < 16; t++) {
        int i = t * 256 + tid;
        int r = i >> 5, c = i & 31;
        int k = k0 + c;
        rA[t] = (k < FC1_IN) ? g_p2[(long)(m0 + r) * FC1_IN + k] : 0.f;
        rB[t] = (r < FC1_OUT && k < FC1_IN) ? wfc[(long)r * FC1_IN + k] : 0.f;
    }

#pragma unroll 1
    for (int step = 0; step < KCHUNK / KT; step++) {
#pragma unroll
        for (int t = 0; t < 16; t++) {
            int i = t * 256 + tid;
            int r = i >> 5, c = i & 31;
            As[r][c] = rA[t];
            Bs[c][r] = rB[t];
        }
        __syncthreads();

        int k1 = k0 + KT;
        if (step + 1 < KCHUNK / KT) {
#pragma unroll
            for (int t = 0; t < 16; t++) {
                int i = t * 256 + tid;
                int r = i >> 5, c = i & 31;
                int k = k1 + c;
                rA[t] = (k < FC1_IN) ? g_p2[(long)(m0 + r) * FC1_IN + k] : 0.f;
                rB[t] = (r < FC1_OUT && k < FC1_IN) ? wfc[(long)r * FC1_IN + k] : 0.f;
            }
        }

#pragma unroll 4
        for (int kk = 0; kk < KT; kk++) {
            ull b2[4], a2[8];
            const ull* bp = (const ull*)&Bs[kk][0];
#pragma unroll
            for (int q = 0; q < 4; q++) b2[q] = bp[tx + 16 * q];
#pragma unroll
            for (int i = 0; i < 8; i++) { float av = As[ty + 16 * i][kk]; a2[i] = pk2(av, av); }
#pragma unroll
            for (int i = 0; i < 8; i++)
#pragma unroll
                for (int q = 0; q < 4; q++) fma2(acc[i][q], a2[i], b2[q]);
        }
        k0 = k1;
        __syncthreads();
    }

#pragma unroll
    for (int i = 0; i < 8; i++) {
        int m = m0 + ty + 16 * i;
#pragma unroll
        for (int q = 0; q < 4; q++) {
            float lo, hi; upk2(lo, hi, acc[i][q]);
            int n = 2 * (tx + 16 * q);
            if (n < FC1_OUT)     g_fc1p[((long)kb * BATCH + m) * FC1_OUT + n]     = lo;
            if (n + 1 < FC1_OUT) g_fc1p[((long)kb * BATCH + m) * FC1_OUT + n + 1] = hi;
        }
    }
}

__global__ void fc1_reduce_kernel(const float* __restrict__ bias) {
    int idx = blockIdx.x * blockDim.x + threadIdx.x;
    if (idx >= BATCH * FC1_OUT) return;
    int n = idx % FC1_OUT;
    float s = bias[n];
#pragma unroll 2
    for (int kb = 0; kb < KSPLIT; kb++)
        s += g_fc1p[(long)kb * BATCH * FC1_OUT + idx];
    g_h1[idx] = fmaxf(s, 0.f);
}

// ================= fc2 + head fused =================
__global__ __launch_bounds__(128)
void fc2_head_kernel(const float* __restrict__ w, const float* __restrict__ bias,
                     const float* __restrict__ fc3w, const float* __restrict__ fc3b,
                     const float* __restrict__ plw, const float* __restrict__ plb,
                     const float* __restrict__ pls, const float* __restrict__ plbias) {
    int b = blockIdx.x;
    int tid = threadIdx.x;
    __shared__ float h[FC1_OUT];
    __shared__ float fs[FC2_OUT];
    __shared__ float wsum[4];

    if (tid < FC1_OUT) h[tid] = g_h1[b * FC1_OUT + tid];
    __syncthreads();
    if (tid < FC2_OUT) {
        float s = bias[tid];
        const float* wr = w + tid * FC1_OUT;
#pragma unroll 8
        for (int k = 0; k < FC1_OUT; k++) s = fmaf(h[k], wr[k], s);
        fs[tid] = s;
        g_feat[b * FC2_OUT + tid] = s;
    }
    __syncthreads();

    float p = (tid < FC2_OUT) ? fs[tid] * fc3w[tid] : 0.f;
#pragma unroll
    for (int o = 16; o > 0; o >>= 1) p += __shfl_xor_sync(0xffffffff, p, o);
    if ((tid & 31) == 0) wsum[tid >> 5] = p;
    __syncthreads();
    if (tid == 0) {
        float s = wsum[0] + wsum[1] + wsum[2] + wsum[3] + fc3b[0];
        float z = tanhf(s * plw[0] + plb[0]) * pls[0] + plbias[0];
        g_probs[b] = 1.f / (1.f + expf(-z));
    }
}

// ====== graph aggregation (sign(dot) == sign(sim), THRESH=0), shuffle reduction ========
__global__ void graph_kernel(float* __restrict__ out) {
    int i = blockIdx.x;
    int j = threadIdx.x;
    __shared__ float fi[FC2_OUT];
    __shared__ float wdeg[8];
    __shared__ float wsm[8];
    if (j < FC2_OUT) fi[j] = g_feat[i * FC2_OUT + j];
    __syncthreads();

    float dot = 0.f;
#pragma unroll 4
    for (int k = 0; k < FC2_OUT; k++) dot = fmaf(fi[k], g_feat[j * FC2_OUT + k], dot);
    float a = (dot >= 0.f && i != j) ? 1.f : 0.f;
    float s = a * g_probs[j];

#pragma unroll
    for (int o = 16; o > 0; o >>= 1) {
        a += __shfl_xor_sync(0xffffffff, a, o);
        s += __shfl_xor_sync(0xffffffff, s, o);
    }
    if ((j & 31) == 0) { wdeg[j >> 5] = a; wsm[j >> 5] = s; }
    __syncthreads();
    if (j == 0) {
        float deg = 0.f, sm = 0.f;
#pragma unroll
        for (int w = 0; w < 8; w++) { deg += wdeg[w]; sm += wsm[w]; }
        float nm  = (deg > 0.f) ? (sm / fmaxf(deg, 1.f)) : 0.f;
        float agg = (g_probs[i] + nm) / (1.f + deg);
        out[i * 2 + 0] = agg;
        out[i * 2 + 1] = 1.f - agg;
    }
}

// ================= launch =================
extern "C" void kernel_launch(void* const* d_in, const int* in_sizes, int n_in,
                              void* d_out, int out_size) {
    const float* x       = (const float*)d_in[0];
    const float* conv1_w = (const float*)d_in[1];
    const float* conv1_b = (const float*)d_in[2];
    const float* conv2_w = (const float*)d_in[3];
    const float* conv2_b = (const float*)d_in[4];
    const float* fc1_w   = (const float*)d_in[5];
    const float* fc1_b   = (const float*)d_in[6];
    const float* fc2_w   = (const float*)d_in[7];
    const float* fc2_b   = (const float*)d_in[8];
    const float* fc3_w   = (const float*)d_in[9];
    const float* fc3_b   = (const float*)d_in[10];
    const float* pl_w    = (const float*)d_in[11];
    const float* pl_b    = (const float*)d_in[12];
    const float* pl_s    = (const float*)d_in[13];
    const float* pl_bias = (const float*)d_in[14];
    float* out = (float*)d_out;

    cudaFuncSetAttribute(conv1_pool_kernel,
                         cudaFuncAttributeMaxDynamicSharedMemorySize, C1_SMEM_BYTES);
    cudaFuncSetAttribute(conv2_pool_kernel,
                         cudaFuncAttributeMaxDynamicSharedMemorySize, C2_SMEM_BYTES);

    // prep: pack into device globals (2 kernel launches), then D2D-copy to __constant__
    pack_w1_kernel<<<1, 256>>>(conv1_w, conv1_b);     // launch 0
    pack_w2_kernel<<<1, 448>>>(conv2_w, conv2_b);     // launch 1
    {
        void *pw1, *pw2, *pb1, *pb2;
        cudaGetSymbolAddress(&pw1, g_w1p);
        cudaGetSymbolAddress(&pw2, g_w2p);
        cudaGetSymbolAddress(&pb1, g_b1);
        cudaGetSymbolAddress(&pb2, g_b2);
        cudaMemcpyToSymbolAsync(c_w1, pw1, sizeof(float2) * C1_IC * 25 * C1_NP, 0,
                                cudaMemcpyDeviceToDevice, 0);
        cudaMemcpyToSymbolAsync(c_w2, pw2, sizeof(float2) * C2_IC * 9 * C2_NP, 0,
                                cudaMemcpyDeviceToDevice, 0);
        cudaMemcpyToSymbolAsync(c_b1, pb1, sizeof(float) * 8, 0,
                                cudaMemcpyDeviceToDevice, 0);
        cudaMemcpyToSymbolAsync(c_b2, pb2, sizeof(float) * 16, 0,
                                cudaMemcpyDeviceToDevice, 0);
    }

    {   // conv1 + relu + pool1 (fused) — launch 2
        dim3 grd((P1_OH + C1_TPX - 1) / C1_TPX, (P1_OH + C1_TPY - 1) / C1_TPY, BATCH);
        conv1_pool_kernel<<<grd, C1_T, C1_SMEM_BYTES>>>(x);
    }
    {   // conv2 + relu + pool2 (fused) — launch 3 (profiled)
        dim3 grd((P2_OH + C2_TPX - 1) / C2_TPX, (P2_OH + C2_TPY - 1) / C2_TPY, BATCH);
        conv2_pool_kernel<<<grd, C2_T, C2_SMEM_BYTES>>>();
    }
    // fc1 (one wave: 148 blocks) + reduce
    {
        dim3 grd(2, KSPLIT);
        fc1_kernel<<<grd, 256>>>(fc1_w);
        fc1_reduce_kernel<<<(BATCH * FC1_OUT + 127) / 128, 128>>>(fc1_b);
    }
    fc2_head_kernel<<<BATCH, 128>>>(fc2_w, fc2_b, fc3_w, fc3_b, pl_w, pl_b, pl_s, pl_bias);
    graph_kernel<<<BATCH, BATCH>>>(out);
}